// round 7
// baseline (speedup 1.0000x reference)
#include <cuda_runtime.h>

#define DIMS 2048
#define SEQ  4096
#define SENT 2.0f            // tanh output in (-1,1), h0 = 0 -> never 2.0
#define NCTA 128
#define RNN_T 512            // 16 warps, 1 row per warp

// ---------------- scratch (static device globals; no allocation) ------------
__device__ float g_A[SEQ * DIMS];                         // A = X @ W_hi^T + b
__device__ __align__(16) float g_hist[(SEQ + 1) * DIMS];  // write-once h history

// ---------------- asm helpers ------------------------------------------------
__device__ __forceinline__ float tanh_fast(float x) {
    float y; asm("tanh.approx.f32 %0, %1;" : "=f"(y) : "f"(x)); return y;
}
__device__ __forceinline__ float4 ldg_vol_v4(const float4* p) {
    float4 v;
    asm volatile("ld.volatile.global.v4.f32 {%0,%1,%2,%3}, [%4];"
                 : "=f"(v.x), "=f"(v.y), "=f"(v.z), "=f"(v.w) : "l"(p));
    return v;
}
__device__ __forceinline__ void stg_vol_f32(float* p, float v) {
    asm volatile("st.volatile.global.f32 [%0], %1;" :: "l"(p), "f"(v) : "memory");
}
__device__ __forceinline__ void ffma2(unsigned long long& d,
                                      unsigned long long a, unsigned long long b) {
    asm("fma.rn.f32x2 %0, %1, %2, %0;" : "+l"(d) : "l"(a), "l"(b));
}
__device__ __forceinline__ unsigned long long add2(unsigned long long a,
                                                   unsigned long long b) {
    unsigned long long s;
    asm("add.rn.f32x2 %0, %1, %2;" : "=l"(s) : "l"(a), "l"(b));
    return s;
}
__device__ __forceinline__ unsigned long long pack2(float x) {
    unsigned long long r; asm("mov.b64 %0, {%1, %1};" : "=l"(r) : "f"(x)); return r;
}
__device__ __forceinline__ float hsum4(unsigned long long a, unsigned long long b,
                                       unsigned long long c, unsigned long long d) {
    unsigned long long s = add2(add2(a, b), add2(c, d));
    float2 f = *reinterpret_cast<float2*>(&s);
    return f.x + f.y;
}

// ---------------- init: poison history, seed h0 -------------------------------
__global__ void poison_kernel() {
    const float4 s = make_float4(SENT, SENT, SENT, SENT);
    float4* p = (float4*)g_hist;
    const int total = (SEQ + 1) * (DIMS / 4);
    for (int w = blockIdx.x * blockDim.x + threadIdx.x; w < total;
         w += gridDim.x * blockDim.x)
        p[w] = s;
}
__global__ void seed_kernel(const float* __restrict__ h0) {
    int i = blockIdx.x * blockDim.x + threadIdx.x;
    if (i < DIMS) g_hist[i] = h0[i];
}

// ---------------- phase 1: A = X @ W^T + b  (packed f32x2 GEMM, as R5) --------
#define BM 128
#define BN 128
#define BK 8

__global__ __launch_bounds__(256) void gemm_kernel(
    const float* __restrict__ X, const float* __restrict__ W,
    const float* __restrict__ b, float* __restrict__ A)
{
    __shared__ __align__(16) float Xs[BK][BM];
    __shared__ __align__(16) float Ws[BK][BN];

    const int tid = threadIdx.x;
    const int m0  = blockIdx.y * BM;
    const int n0  = blockIdx.x * BN;
    const int tx  = tid & 15;
    const int ty  = tid >> 4;
    const int lr  = tid >> 1;
    const int lk  = (tid & 1) * 4;

    unsigned long long acc[8][4];
#pragma unroll
    for (int i = 0; i < 8; i++)
#pragma unroll
        for (int jp = 0; jp < 4; jp++) acc[i][jp] = 0ull;

    for (int k0 = 0; k0 < DIMS; k0 += BK) {
        float4 xv = *(const float4*)(X + (size_t)(m0 + lr) * DIMS + k0 + lk);
        float4 wv = *(const float4*)(W + (size_t)(n0 + lr) * DIMS + k0 + lk);
        __syncthreads();
        Xs[lk + 0][lr] = xv.x; Xs[lk + 1][lr] = xv.y;
        Xs[lk + 2][lr] = xv.z; Xs[lk + 3][lr] = xv.w;
        Ws[lk + 0][lr] = wv.x; Ws[lk + 1][lr] = wv.y;
        Ws[lk + 2][lr] = wv.z; Ws[lk + 3][lr] = wv.w;
        __syncthreads();
#pragma unroll
        for (int k = 0; k < BK; k++) {
            unsigned long long xd[8], wp[4];
#pragma unroll
            for (int i = 0; i < 8; i++) xd[i] = pack2(Xs[k][ty + 16 * i]);
#pragma unroll
            for (int jp = 0; jp < 4; jp++)
                wp[jp] = *(const unsigned long long*)&Ws[k][tx * 2 + 32 * jp];
#pragma unroll
            for (int i = 0; i < 8; i++)
#pragma unroll
                for (int jp = 0; jp < 4; jp++) ffma2(acc[i][jp], xd[i], wp[jp]);
        }
    }
    unsigned long long bp[4];
#pragma unroll
    for (int jp = 0; jp < 4; jp++)
        bp[jp] = *(const unsigned long long*)&b[n0 + tx * 2 + 32 * jp];
#pragma unroll
    for (int i = 0; i < 8; i++) {
        const int m = m0 + ty + 16 * i;
#pragma unroll
        for (int jp = 0; jp < 4; jp++) {
            *(unsigned long long*)&A[(size_t)m * DIMS + n0 + tx * 2 + 32 * jp] =
                add2(acc[i][jp], bp[jp]);
        }
    }
}

// ---------------- phase 2: persistent sequential RNN --------------------------
// 128 CTAs x 512 threads (16 warps, 1 h-row each), 1 CTA/SM. Value-signaled
// exchange: write-once history, sentinel poison, payload-polling. One bar per
// step (double-buffered h_s), single-float volatile publish per warp.
__global__ __launch_bounds__(RNN_T, 1) void rnn_kernel(
    const float* __restrict__ X, const float* __restrict__ Whh,
    float* __restrict__ out)
{
    __shared__ __align__(16) float4 h_s[2][DIMS / 4];   // 2 x 8 KB

    const int tid  = threadIdx.x;
    const int wid  = tid >> 5;
    const int lane = tid & 31;
    const int row  = blockIdx.x * 16 + wid;

    // This warp's W_hh row in registers as packed f32x2 pairs (64 f32/lane).
    ulonglong2 w[16];
    {
        const ulonglong2* Wr = (const ulonglong2*)(Whh + (size_t)row * DIMS);
#pragma unroll
        for (int k = 0; k < 16; k++) w[k] = Wr[lane + 32 * k];
    }

    for (int t = 0; t < SEQ; t++) {
        const int cur = t & 1;
        const float4* hb = (const float4*)(g_hist + (size_t)t * DIMS);

        // Step-constant operands, off the h critical chain.
        float a = 0.f, xr = 0.f;
        if (lane == 0) {
            a  = g_A[(size_t)t * DIMS + row];
            xr = X[(size_t)t * DIMS + row];
        }

        // Ingest h_prev: each thread owns ONE 16B word; payload IS the signal.
        // Backoff after 2 failed tries to cut redundant LTS poll traffic.
        {
            float4 v = ldg_vol_v4(hb + tid);
            if (v.x == SENT || v.y == SENT || v.z == SENT || v.w == SENT) {
                v = ldg_vol_v4(hb + tid);
                while (v.x == SENT || v.y == SENT || v.z == SENT || v.w == SENT) {
                    __nanosleep(32);
                    v = ldg_vol_v4(hb + tid);
                }
            }
            h_s[cur][tid] = v;
        }
        __syncthreads();   // the ONLY bar: h_s[cur] staged. (Reaching this bar
                           // at t also proves everyone finished reading
                           // h_s[t-1 parity], so t+1 may overwrite it barless.)

        // One 2048-dot per warp; W in registers, h broadcast from smem,
        // packed f32x2 FMA, 4 accumulator chains of depth 8.
        const ulonglong2* hp = (const ulonglong2*)h_s[cur];
        unsigned long long ax0 = 0ull, ay0 = 0ull, ax1 = 0ull, ay1 = 0ull;
#pragma unroll
        for (int k = 0; k < 16; k += 2) {
            ulonglong2 hv0 = hp[lane + 32 * k];
            ulonglong2 hv1 = hp[lane + 32 * (k + 1)];
            ffma2(ax0, w[k].x,     hv0.x);  ffma2(ay0, w[k].y,     hv0.y);
            ffma2(ax1, w[k + 1].x, hv1.x);  ffma2(ay1, w[k + 1].y, hv1.y);
        }
        float acc = hsum4(ax0, ay0, ax1, ay1);
#pragma unroll
        for (int o = 16; o > 0; o >>= 1)
            acc += __shfl_xor_sync(0xffffffffu, acc, o);

        if (lane == 0) {
            float hn = tanh_fast(a + acc);
            stg_vol_f32(g_hist + (size_t)(t + 1) * DIMS + row, hn);  // publish 1st
            out[(size_t)t * DIMS + row] = xr + hn;                   // residual
        }
    }
}

// ---------------- launch -------------------------------------------------------
extern "C" void kernel_launch(void* const* d_in, const int* in_sizes, int n_in,
                              void* d_out, int out_size) {
    const float* X    = (const float*)d_in[0];  // [SEQ, DIMS]
    const float* W_hi = (const float*)d_in[1];  // [DIMS, DIMS]
    const float* W_hh = (const float*)d_in[2];  // [DIMS, DIMS]
    const float* b    = (const float*)d_in[3];  // [DIMS]
    const float* h0   = (const float*)d_in[4];  // [DIMS]
    float* out = (float*)d_out;

    float* A;
    cudaGetSymbolAddress((void**)&A, g_A);

    poison_kernel<<<1024, 256>>>();
    seed_kernel<<<(DIMS + 255) / 256, 256>>>(h0);

    dim3 ggrid(DIMS / BN, SEQ / BM);            // (16, 32)
    gemm_kernel<<<ggrid, 256>>>(X, W_hi, b, A);

    rnn_kernel<<<NCTA, RNN_T>>>(X, W_hh, out);
}